// round 3
// baseline (speedup 1.0000x reference)
#include <cuda_runtime.h>
#include <stdint.h>

// Problem constants (fixed by the dataset)
#define NPTS      32768
#define NKERN     4
#define GRID      16
#define C_IN      64
#define C_OUT     64
#define NCELLS    (NKERN * GRID * GRID * GRID)   // 16384
#define NENT      (NPTS * 8)                     // 262144

// ---------------------------------------------------------------------------
// Device scratch (static __device__ globals: allowed; no cudaMalloc anywhere)
// ---------------------------------------------------------------------------
__device__ unsigned g_counts[NCELLS];
__device__ unsigned g_offsets[NCELLS + 1];
__device__ unsigned g_cursor[NCELLS];
__device__ unsigned g_cells[NENT];     // cell id per (point,corner) entry
__device__ float    g_wts[NENT];       // trilinear weight per entry
__device__ unsigned g_sorted[NENT];    // entry ids grouped by cell
__device__ float    g_contrib[(size_t)NENT * C_OUT];  // 67MB staging (deterministic)

// ---------------------------------------------------------------------------
// K0: zero the histogram
// ---------------------------------------------------------------------------
__global__ void k_zero_counts() {
    int i = blockIdx.x * blockDim.x + threadIdx.x;
    if (i < NCELLS) g_counts[i] = 0u;
}

// ---------------------------------------------------------------------------
// K1: per-point corner cells + weights, histogram cells
// ---------------------------------------------------------------------------
__global__ void k_prep(const int* __restrict__ pidx,
                       const float* __restrict__ pos) {
    int n = blockIdx.x * blockDim.x + threadIdx.x;
    if (n >= NPTS) return;

    float lx = pos[n * 3 + 0] * (float)GRID - 0.5f;
    float ly = pos[n * 3 + 1] * (float)GRID - 0.5f;
    float lz = pos[n * 3 + 2] * (float)GRID - 0.5f;
    float fx = floorf(lx), fy = floorf(ly), fz = floorf(lz);
    float cwx = lx - fx, cwy = ly - fy, cwz = lz - fz;
    float fwx = 1.f - cwx, fwy = 1.f - cwy, fwz = 1.f - cwz;
    int ix = (int)fx, iy = (int)fy, iz = (int)fz;   // may be -1..15
    int pi = pidx[n];

    #pragma unroll
    for (int k = 0; k < 8; k++) {
        int bx = k & 1, by = (k >> 1) & 1, bz = (k >> 2) & 1;
        int jx = min(max(ix + bx, 0), GRID - 1);
        int jy = min(max(iy + by, 0), GRID - 1);
        int jz = min(max(iz + bz, 0), GRID - 1);
        float w = (bx ? cwx : fwx) * (by ? cwy : fwy) * (bz ? cwz : fwz);
        // reference indexes kernels[pidx, idx_z, idx_y, idx_x]
        unsigned cell = (((unsigned)pi * GRID + jz) * GRID + jy) * GRID + jx;
        g_cells[n * 8 + k] = cell;
        g_wts[n * 8 + k] = w;
        atomicAdd(&g_counts[cell], 1u);
    }
}

// ---------------------------------------------------------------------------
// K2: single-block exclusive scan of 16384 counts (512 thr x 32 elems)
// ---------------------------------------------------------------------------
__global__ void k_scan() {
    __shared__ unsigned part[512];
    int t = threadIdx.x;
    unsigned sum = 0;
    #pragma unroll 4
    for (int i = 0; i < 32; i++) sum += g_counts[t * 32 + i];
    part[t] = sum;
    __syncthreads();
    // Hillis-Steele inclusive scan over 512 partials
    for (int off = 1; off < 512; off <<= 1) {
        unsigned v = 0;
        if (t >= off) v = part[t - off];
        __syncthreads();
        if (t >= off) part[t] += v;
        __syncthreads();
    }
    unsigned run = (t == 0) ? 0u : part[t - 1];
    #pragma unroll 4
    for (int i = 0; i < 32; i++) {
        int idx = t * 32 + i;
        g_offsets[idx] = run;
        g_cursor[idx] = run;
        run += g_counts[idx];
    }
    if (t == 511) g_offsets[NCELLS] = run;   // == NENT
}

// ---------------------------------------------------------------------------
// K3: scatter entries into cell-grouped order
// ---------------------------------------------------------------------------
__global__ void k_scatter() {
    int e = blockIdx.x * blockDim.x + threadIdx.x;
    if (e >= NENT) return;
    unsigned cell = g_cells[e];
    unsigned slot = atomicAdd(&g_cursor[cell], 1u);
    g_sorted[slot] = (unsigned)e;
}

// ---------------------------------------------------------------------------
// K4: per-cell GEMM.  One CTA (128 thr) per cell.
//     K (64x64) lives in SMEM; entries processed in batches of 16 with a
//     2x4 register tile per thread (LDS.64 y + LDS.128 K + 8 FFMA per c).
//     contrib[e][f] = w_e * (x_e @ K + b)     (written once; deterministic)
// ---------------------------------------------------------------------------
#define YSTRIDE 20   // 16 slots, padded; keeps float2 8B-aligned, few conflicts

__global__ __launch_bounds__(128) void k_cell_gemm(
    const float* __restrict__ xs,
    const float* __restrict__ kernels,
    const float* __restrict__ biases) {

    int cell = blockIdx.x;
    int start = (int)g_offsets[cell];
    int nent  = (int)g_offsets[cell + 1] - start;
    if (nent == 0) return;

    __shared__ __align__(16) float ksm[C_IN * C_OUT];   // 16KB
    __shared__ __align__(16) float ysm[C_IN * YSTRIDE]; // 5KB
    __shared__ float    bsm[C_OUT];
    __shared__ float    wsm[16];
    __shared__ unsigned esm[16];

    int t = threadIdx.x;                 // 128 threads
    int fj = t & 15;                     // 16 column groups of 4 -> 64 cols
    int ei = t >> 4;                     // 8 entry groups of 2 -> 16 slots

    // stage K (coalesced float4) and bias
    const float* kg = kernels + (size_t)cell * (C_IN * C_OUT);
    #pragma unroll
    for (int i = t; i < (C_IN * C_OUT) / 4; i += 128)
        ((float4*)ksm)[i] = ((const float4*)kg)[i];
    if (t < C_OUT) bsm[t] = biases[(size_t)cell * C_OUT + t];

    for (int base = 0; base < nent; base += 16) {
        int nb = min(16, nent - base);

        __syncthreads();   // prior batch done reading ysm/esm; K staged (1st iter)
        if (t < 16) {
            unsigned e = 0xFFFFFFFFu;
            float w = 0.f;
            if (t < nb) { e = g_sorted[start + base + t]; w = g_wts[e]; }
            esm[t] = e;
            wsm[t] = w;
        }
        __syncthreads();

        // stage y[c][slot] = w * x[pt][c]   (coalesced reads of xs rows)
        for (int i = t; i < 16 * C_IN; i += 128) {
            int c = i & 63, s = i >> 6;
            unsigned e = esm[s];
            float v = 0.f;
            if (e != 0xFFFFFFFFu) v = wsm[s] * xs[(size_t)(e >> 3) * C_IN + c];
            ysm[c * YSTRIDE + s] = v;
        }
        __syncthreads();

        float acc[2][4] = {{0.f,0.f,0.f,0.f},{0.f,0.f,0.f,0.f}};
        const int yb = ei * 2;
        const int kb = fj * 4;
        #pragma unroll 8
        for (int c = 0; c < C_IN; c++) {
            float2 y2 = *(const float2*)&ysm[c * YSTRIDE + yb];
            float4 k4 = *(const float4*)&ksm[c * C_OUT + kb];
            acc[0][0] += y2.x * k4.x; acc[0][1] += y2.x * k4.y;
            acc[0][2] += y2.x * k4.z; acc[0][3] += y2.x * k4.w;
            acc[1][0] += y2.y * k4.x; acc[1][1] += y2.y * k4.y;
            acc[1][2] += y2.y * k4.z; acc[1][3] += y2.y * k4.w;
        }

        #pragma unroll
        for (int j = 0; j < 2; j++) {
            int slot = yb + j;
            if (slot < nb) {
                unsigned e = esm[slot];
                float w = wsm[slot];
                float4 o;
                o.x = acc[j][0] + w * bsm[kb + 0];
                o.y = acc[j][1] + w * bsm[kb + 1];
                o.z = acc[j][2] + w * bsm[kb + 2];
                o.w = acc[j][3] + w * bsm[kb + 3];
                *(float4*)&g_contrib[(size_t)e * C_OUT + kb] = o;
            }
        }
    }
}

// ---------------------------------------------------------------------------
// K5: deterministic reduction of the 8 corner contributions per point
// ---------------------------------------------------------------------------
__global__ void k_reduce(float* __restrict__ out) {
    int i = blockIdx.x * blockDim.x + threadIdx.x;
    if (i >= NPTS * C_OUT) return;
    int n = i >> 6, f = i & 63;
    float s = 0.f;
    #pragma unroll
    for (int k = 0; k < 8; k++)
        s += g_contrib[((size_t)(n * 8 + k)) * C_OUT + f];
    out[i] = s;
}

// ---------------------------------------------------------------------------
// Launcher (graph-capturable: kernels only, default stream)
// ---------------------------------------------------------------------------
extern "C" void kernel_launch(void* const* d_in, const int* in_sizes, int n_in,
                              void* d_out, int out_size) {
    const int*   pidx    = (const int*)  d_in[0];  // (N,1) int32
    const float* pos     = (const float*)d_in[1];  // (N,3)
    const float* xs      = (const float*)d_in[2];  // (N,64)
    const float* kernels = (const float*)d_in[3];  // (4,16,16,16,64,64)
    const float* biases  = (const float*)d_in[4];  // (4,16,16,16,64)
    float* out = (float*)d_out;                    // (N,64)
    (void)in_sizes; (void)n_in; (void)out_size;

    k_zero_counts<<<(NCELLS + 255) / 256, 256>>>();
    k_prep<<<(NPTS + 255) / 256, 256>>>(pidx, pos);
    k_scan<<<1, 512>>>();
    k_scatter<<<(NENT + 255) / 256, 256>>>();
    k_cell_gemm<<<NCELLS, 128>>>(xs, kernels, biases);
    k_reduce<<<(NPTS * C_OUT + 255) / 256, 256>>>(out);
}

// round 4
// speedup vs baseline: 1.1096x; 1.1096x over previous
#include <cuda_runtime.h>
#include <stdint.h>

// Problem constants (fixed by the dataset)
#define NPTS      32768
#define NKERN     4
#define GRID      16
#define C_IN      64
#define C_OUT     64
#define NCELLS    (NKERN * GRID * GRID * GRID)   // 16384
#define NENT      (NPTS * 8)                     // 262144

// ---------------------------------------------------------------------------
// Device scratch (static __device__ globals: allowed; no cudaMalloc anywhere)
// ---------------------------------------------------------------------------
__device__ unsigned g_counts[NCELLS];
__device__ unsigned g_offsets[NCELLS + 1];
__device__ unsigned g_cursor[NCELLS];
__device__ unsigned g_cells[NENT];     // cell id per (point,corner) entry
__device__ float    g_wts[NENT];       // trilinear weight per entry
__device__ unsigned g_sorted[NENT];    // entry ids grouped by cell
__device__ float    g_contrib[(size_t)NENT * C_OUT];  // 67MB staging (deterministic)

// ---------------------------------------------------------------------------
// K0: zero the histogram
// ---------------------------------------------------------------------------
__global__ void k_zero_counts() {
    int i = blockIdx.x * blockDim.x + threadIdx.x;
    if (i < NCELLS) g_counts[i] = 0u;
}

// ---------------------------------------------------------------------------
// K1: per-point corner cells + weights, histogram cells
// ---------------------------------------------------------------------------
__global__ void k_prep(const int* __restrict__ pidx,
                       const float* __restrict__ pos) {
    int n = blockIdx.x * blockDim.x + threadIdx.x;
    if (n >= NPTS) return;

    float lx = pos[n * 3 + 0] * (float)GRID - 0.5f;
    float ly = pos[n * 3 + 1] * (float)GRID - 0.5f;
    float lz = pos[n * 3 + 2] * (float)GRID - 0.5f;
    float fx = floorf(lx), fy = floorf(ly), fz = floorf(lz);
    float cwx = lx - fx, cwy = ly - fy, cwz = lz - fz;
    float fwx = 1.f - cwx, fwy = 1.f - cwy, fwz = 1.f - cwz;
    int ix = (int)fx, iy = (int)fy, iz = (int)fz;   // may be -1..15
    int pi = pidx[n];

    #pragma unroll
    for (int k = 0; k < 8; k++) {
        int bx = k & 1, by = (k >> 1) & 1, bz = (k >> 2) & 1;
        int jx = min(max(ix + bx, 0), GRID - 1);
        int jy = min(max(iy + by, 0), GRID - 1);
        int jz = min(max(iz + bz, 0), GRID - 1);
        float w = (bx ? cwx : fwx) * (by ? cwy : fwy) * (bz ? cwz : fwz);
        // reference indexes kernels[pidx, idx_z, idx_y, idx_x]
        unsigned cell = (((unsigned)pi * GRID + jz) * GRID + jy) * GRID + jx;
        g_cells[n * 8 + k] = cell;
        g_wts[n * 8 + k] = w;
        atomicAdd(&g_counts[cell], 1u);
    }
}

// ---------------------------------------------------------------------------
// K2: single-block exclusive scan of 16384 counts (512 thr x 32 elems)
// ---------------------------------------------------------------------------
__global__ void k_scan() {
    __shared__ unsigned part[512];
    int t = threadIdx.x;
    unsigned sum = 0;
    #pragma unroll 4
    for (int i = 0; i < 32; i++) sum += g_counts[t * 32 + i];
    part[t] = sum;
    __syncthreads();
    // Hillis-Steele inclusive scan over 512 partials
    for (int off = 1; off < 512; off <<= 1) {
        unsigned v = 0;
        if (t >= off) v = part[t - off];
        __syncthreads();
        if (t >= off) part[t] += v;
        __syncthreads();
    }
    unsigned run = (t == 0) ? 0u : part[t - 1];
    #pragma unroll 4
    for (int i = 0; i < 32; i++) {
        int idx = t * 32 + i;
        g_offsets[idx] = run;
        g_cursor[idx] = run;
        run += g_counts[idx];
    }
    if (t == 511) g_offsets[NCELLS] = run;   // == NENT
}

// ---------------------------------------------------------------------------
// K3: scatter entries into cell-grouped order
// ---------------------------------------------------------------------------
__global__ void k_scatter() {
    int e = blockIdx.x * blockDim.x + threadIdx.x;
    if (e >= NENT) return;
    unsigned cell = g_cells[e];
    unsigned slot = atomicAdd(&g_cursor[cell], 1u);
    g_sorted[slot] = (unsigned)e;
}

// ---------------------------------------------------------------------------
// K4: per-cell GEMM.  One CTA (128 thr) per cell.
//     K (64x64) lives in SMEM; entries processed in batches of 16 with a
//     2x4 register tile per thread (LDS.64 y + LDS.128 K + 8 FFMA per c).
//     Warps whose 4 entry-slots are all padding skip the FFMA loop entirely,
//     so effective padding granularity is 4 slots, not 16.
//     contrib[e][f] = w_e * (x_e @ K + b)     (written once; deterministic)
// ---------------------------------------------------------------------------
#define YSTRIDE 20   // 16 slots, padded; keeps float2 8B-aligned, few conflicts

__global__ __launch_bounds__(128) void k_cell_gemm(
    const float* __restrict__ xs,
    const float* __restrict__ kernels,
    const float* __restrict__ biases) {

    int cell = blockIdx.x;
    int start = (int)g_offsets[cell];
    int nent  = (int)g_offsets[cell + 1] - start;
    if (nent == 0) return;

    __shared__ __align__(16) float ksm[C_IN * C_OUT];   // 16KB
    __shared__ __align__(16) float ysm[C_IN * YSTRIDE]; // 5KB
    __shared__ float    bsm[C_OUT];
    __shared__ float    wsm[16];
    __shared__ unsigned esm[16];

    int t = threadIdx.x;                 // 128 threads
    int fj = t & 15;                     // 16 column groups of 4 -> 64 cols
    int ei = t >> 4;                     // 8 entry groups of 2 -> 16 slots
    const int yb = ei * 2;               // first of this thread's 2 slots
    const int kb = fj * 4;               // first of this thread's 4 columns

    // stage K (coalesced float4) and bias
    const float* kg = kernels + (size_t)cell * (C_IN * C_OUT);
    #pragma unroll
    for (int i = t; i < (C_IN * C_OUT) / 4; i += 128)
        ((float4*)ksm)[i] = ((const float4*)kg)[i];
    if (t < C_OUT) bsm[t] = biases[(size_t)cell * C_OUT + t];

    for (int base = 0; base < nent; base += 16) {
        int nb = min(16, nent - base);

        __syncthreads();   // prior batch done reading ysm/esm; K staged (1st iter)
        if (t < 16) {
            unsigned e = 0xFFFFFFFFu;
            float w = 0.f;
            if (t < nb) { e = g_sorted[start + base + t]; w = g_wts[e]; }
            esm[t] = e;
            wsm[t] = w;
        }
        __syncthreads();

        // stage y[c][slot] = w * x[pt][c]  (coalesced reads of xs rows)
        // only slots < nb need real data; others zero-filled (cheap, only
        // touched by straddling warps).
        for (int i = t; i < 16 * C_IN; i += 128) {
            int c = i & 63, s = i >> 6;
            unsigned e = esm[s];
            float v = 0.f;
            if (e != 0xFFFFFFFFu) v = wsm[s] * xs[(size_t)(e >> 3) * C_IN + c];
            ysm[c * YSTRIDE + s] = v;
        }
        __syncthreads();

        // Warp w owns slots [4w, 4w+4). If all its slots are padding
        // (yb >= nb for both its ei values), the whole warp skips the
        // 64-step FFMA loop -> padding cost granularity is 4 slots.
        if (yb < nb) {
            float acc[2][4] = {{0.f,0.f,0.f,0.f},{0.f,0.f,0.f,0.f}};
            #pragma unroll 8
            for (int c = 0; c < C_IN; c++) {
                float2 y2 = *(const float2*)&ysm[c * YSTRIDE + yb];
                float4 k4 = *(const float4*)&ksm[c * C_OUT + kb];
                acc[0][0] += y2.x * k4.x; acc[0][1] += y2.x * k4.y;
                acc[0][2] += y2.x * k4.z; acc[0][3] += y2.x * k4.w;
                acc[1][0] += y2.y * k4.x; acc[1][1] += y2.y * k4.y;
                acc[1][2] += y2.y * k4.z; acc[1][3] += y2.y * k4.w;
            }

            #pragma unroll
            for (int j = 0; j < 2; j++) {
                int slot = yb + j;
                if (slot < nb) {
                    unsigned e = esm[slot];
                    float w = wsm[slot];
                    float4 o;
                    o.x = acc[j][0] + w * bsm[kb + 0];
                    o.y = acc[j][1] + w * bsm[kb + 1];
                    o.z = acc[j][2] + w * bsm[kb + 2];
                    o.w = acc[j][3] + w * bsm[kb + 3];
                    *(float4*)&g_contrib[(size_t)e * C_OUT + kb] = o;
                }
            }
        }
    }
}

// ---------------------------------------------------------------------------
// K5: deterministic reduction of the 8 corner contributions per point.
//     float4 per thread: 8 independent LDG.128 (MLP=8) + 1 STG.128.
// ---------------------------------------------------------------------------
__global__ void k_reduce(float* __restrict__ out) {
    int i = blockIdx.x * blockDim.x + threadIdx.x;   // over NPTS*16 float4s
    if (i >= NPTS * (C_OUT / 4)) return;
    int n = i >> 4, q = i & 15;

    const float4* cp = (const float4*)g_contrib;
    size_t base = (size_t)n * 8 * (C_OUT / 4) + q;

    float4 v0 = cp[base + 0 * (C_OUT / 4)];
    float4 v1 = cp[base + 1 * (C_OUT / 4)];
    float4 v2 = cp[base + 2 * (C_OUT / 4)];
    float4 v3 = cp[base + 3 * (C_OUT / 4)];
    float4 v4 = cp[base + 4 * (C_OUT / 4)];
    float4 v5 = cp[base + 5 * (C_OUT / 4)];
    float4 v6 = cp[base + 6 * (C_OUT / 4)];
    float4 v7 = cp[base + 7 * (C_OUT / 4)];

    float4 s;
    s.x = ((v0.x + v1.x) + (v2.x + v3.x)) + ((v4.x + v5.x) + (v6.x + v7.x));
    s.y = ((v0.y + v1.y) + (v2.y + v3.y)) + ((v4.y + v5.y) + (v6.y + v7.y));
    s.z = ((v0.z + v1.z) + (v2.z + v3.z)) + ((v4.z + v5.z) + (v6.z + v7.z));
    s.w = ((v0.w + v1.w) + (v2.w + v3.w)) + ((v4.w + v5.w) + (v6.w + v7.w));

    ((float4*)out)[i] = s;
}

// ---------------------------------------------------------------------------
// Launcher (graph-capturable: kernels only, default stream)
// ---------------------------------------------------------------------------
extern "C" void kernel_launch(void* const* d_in, const int* in_sizes, int n_in,
                              void* d_out, int out_size) {
    const int*   pidx    = (const int*)  d_in[0];  // (N,1) int32
    const float* pos     = (const float*)d_in[1];  // (N,3)
    const float* xs      = (const float*)d_in[2];  // (N,64)
    const float* kernels = (const float*)d_in[3];  // (4,16,16,16,64,64)
    const float* biases  = (const float*)d_in[4];  // (4,16,16,16,64)
    float* out = (float*)d_out;                    // (N,64)
    (void)in_sizes; (void)n_in; (void)out_size;

    k_zero_counts<<<(NCELLS + 255) / 256, 256>>>();
    k_prep<<<(NPTS + 255) / 256, 256>>>(pidx, pos);
    k_scan<<<1, 512>>>();
    k_scatter<<<(NENT + 255) / 256, 256>>>();
    k_cell_gemm<<<NCELLS, 128>>>(xs, kernels, biases);
    k_reduce<<<(NPTS * (C_OUT / 4) + 255) / 256, 256>>>(out);
}

// round 5
// speedup vs baseline: 1.1130x; 1.0031x over previous
#include <cuda_runtime.h>
#include <stdint.h>

// Problem constants (fixed by the dataset)
#define NPTS      32768
#define NKERN     4
#define GRID      16
#define C_IN      64
#define C_OUT     64
#define NCELLS    (NKERN * GRID * GRID * GRID)   // 16384
#define NENT      (NPTS * 8)                     // 262144

// ---------------------------------------------------------------------------
// Device scratch (static __device__ globals: allowed; no cudaMalloc anywhere)
// ---------------------------------------------------------------------------
__device__ unsigned g_counts[NCELLS];
__device__ unsigned g_offsets[NCELLS + 1];
__device__ unsigned g_cursor[NCELLS];
__device__ unsigned g_cells[NENT];     // cell id per (point,corner) entry
__device__ float    g_wts[NENT];       // trilinear weight per entry
__device__ unsigned g_sorted[NENT];    // entry ids grouped by cell
__device__ float    g_contrib[(size_t)NENT * C_OUT];  // 67MB staging (deterministic)

// packed f32x2 FMA: d = a*b + d  (SASS FFMA2 — 2 fp32 MACs per lane per issue)
__device__ __forceinline__ void ffma2(unsigned long long& d,
                                      unsigned long long a,
                                      unsigned long long b) {
    asm("fma.rn.f32x2 %0, %1, %2, %0;" : "+l"(d) : "l"(a), "l"(b));
}
__device__ __forceinline__ unsigned long long bcast2(float v) {
    unsigned long long r;
    asm("mov.b64 %0, {%1, %1};" : "=l"(r) : "f"(v));
    return r;
}
__device__ __forceinline__ float2 unpack2(unsigned long long v) {
    float2 r;
    asm("mov.b64 {%0, %1}, %2;" : "=f"(r.x), "=f"(r.y) : "l"(v));
    return r;
}

// ---------------------------------------------------------------------------
// K0: zero the histogram
// ---------------------------------------------------------------------------
__global__ void k_zero_counts() {
    int i = blockIdx.x * blockDim.x + threadIdx.x;
    if (i < NCELLS) g_counts[i] = 0u;
}

// ---------------------------------------------------------------------------
// K1: per-point corner cells + weights, histogram cells
// ---------------------------------------------------------------------------
__global__ void k_prep(const int* __restrict__ pidx,
                       const float* __restrict__ pos) {
    int n = blockIdx.x * blockDim.x + threadIdx.x;
    if (n >= NPTS) return;

    float lx = pos[n * 3 + 0] * (float)GRID - 0.5f;
    float ly = pos[n * 3 + 1] * (float)GRID - 0.5f;
    float lz = pos[n * 3 + 2] * (float)GRID - 0.5f;
    float fx = floorf(lx), fy = floorf(ly), fz = floorf(lz);
    float cwx = lx - fx, cwy = ly - fy, cwz = lz - fz;
    float fwx = 1.f - cwx, fwy = 1.f - cwy, fwz = 1.f - cwz;
    int ix = (int)fx, iy = (int)fy, iz = (int)fz;   // may be -1..15
    int pi = pidx[n];

    #pragma unroll
    for (int k = 0; k < 8; k++) {
        int bx = k & 1, by = (k >> 1) & 1, bz = (k >> 2) & 1;
        int jx = min(max(ix + bx, 0), GRID - 1);
        int jy = min(max(iy + by, 0), GRID - 1);
        int jz = min(max(iz + bz, 0), GRID - 1);
        float w = (bx ? cwx : fwx) * (by ? cwy : fwy) * (bz ? cwz : fwz);
        // reference indexes kernels[pidx, idx_z, idx_y, idx_x]
        unsigned cell = (((unsigned)pi * GRID + jz) * GRID + jy) * GRID + jx;
        g_cells[n * 8 + k] = cell;
        g_wts[n * 8 + k] = w;
        atomicAdd(&g_counts[cell], 1u);
    }
}

// ---------------------------------------------------------------------------
// K2: single-block exclusive scan of 16384 counts (512 thr x 32 elems)
// ---------------------------------------------------------------------------
__global__ void k_scan() {
    __shared__ unsigned part[512];
    int t = threadIdx.x;
    unsigned sum = 0;
    #pragma unroll 4
    for (int i = 0; i < 32; i++) sum += g_counts[t * 32 + i];
    part[t] = sum;
    __syncthreads();
    for (int off = 1; off < 512; off <<= 1) {
        unsigned v = 0;
        if (t >= off) v = part[t - off];
        __syncthreads();
        if (t >= off) part[t] += v;
        __syncthreads();
    }
    unsigned run = (t == 0) ? 0u : part[t - 1];
    #pragma unroll 4
    for (int i = 0; i < 32; i++) {
        int idx = t * 32 + i;
        g_offsets[idx] = run;
        g_cursor[idx] = run;
        run += g_counts[idx];
    }
    if (t == 511) g_offsets[NCELLS] = run;   // == NENT
}

// ---------------------------------------------------------------------------
// K3: scatter entries into cell-grouped order
// ---------------------------------------------------------------------------
__global__ void k_scatter() {
    int e = blockIdx.x * blockDim.x + threadIdx.x;
    if (e >= NENT) return;
    unsigned cell = g_cells[e];
    unsigned slot = atomicAdd(&g_cursor[cell], 1u);
    g_sorted[slot] = (unsigned)e;
}

// ---------------------------------------------------------------------------
// K4: per-cell GEMM.  One CTA (128 thr) per cell.
//     K (64x64) in SMEM; batches of 16 entries; 2x4 register tile per thread.
//     Inner loop uses packed fma.rn.f32x2 (FFMA2): 4 packed FMAs replace
//     8 scalar FFMA -> 2x the fp32 fma-pipe throughput.
//     Warps whose 4 entry-slots are all padding skip the loop entirely.
//     contrib[e][f] = w_e * (x_e @ K + b)     (written once; deterministic)
// ---------------------------------------------------------------------------
#define YSTRIDE 20   // 16 slots, padded; keeps float2 8B-aligned, few conflicts

__global__ __launch_bounds__(128) void k_cell_gemm(
    const float* __restrict__ xs,
    const float* __restrict__ kernels,
    const float* __restrict__ biases) {

    int cell = blockIdx.x;
    int start = (int)g_offsets[cell];
    int nent  = (int)g_offsets[cell + 1] - start;
    if (nent == 0) return;

    __shared__ __align__(16) float ksm[C_IN * C_OUT];   // 16KB
    __shared__ __align__(16) float ysm[C_IN * YSTRIDE]; // 5KB
    __shared__ float    bsm[C_OUT];
    __shared__ float    wsm[16];
    __shared__ unsigned esm[16];

    int t = threadIdx.x;                 // 128 threads
    int fj = t & 15;                     // 16 column groups of 4 -> 64 cols
    int ei = t >> 4;                     // 8 entry groups of 2 -> 16 slots
    const int yb = ei * 2;               // first of this thread's 2 slots
    const int kb = fj * 4;               // first of this thread's 4 columns

    // stage K (coalesced float4) and bias
    const float* kg = kernels + (size_t)cell * (C_IN * C_OUT);
    #pragma unroll
    for (int i = t; i < (C_IN * C_OUT) / 4; i += 128)
        ((float4*)ksm)[i] = ((const float4*)kg)[i];
    if (t < C_OUT) bsm[t] = biases[(size_t)cell * C_OUT + t];

    for (int base = 0; base < nent; base += 16) {
        int nb = min(16, nent - base);

        __syncthreads();   // prior batch done reading ysm/esm; K staged (1st iter)
        if (t < 16) {
            unsigned e = 0xFFFFFFFFu;
            float w = 0.f;
            if (t < nb) { e = g_sorted[start + base + t]; w = g_wts[e]; }
            esm[t] = e;
            wsm[t] = w;
        }
        __syncthreads();

        // stage y[c][slot] = w * x[pt][c]  (coalesced reads of xs rows)
        for (int i = t; i < 16 * C_IN; i += 128) {
            int c = i & 63, s = i >> 6;
            unsigned e = esm[s];
            float v = 0.f;
            if (e != 0xFFFFFFFFu) v = wsm[s] * xs[(size_t)(e >> 3) * C_IN + c];
            ysm[c * YSTRIDE + s] = v;
        }
        __syncthreads();

        // Warp w owns slots [4w, 4w+4); all-padding warps skip entirely.
        if (yb < nb) {
            // packed accumulators: aXY = slot X, column-pair Y
            // a00 = (col kb+0, col kb+1) of slot0 ; a01 = (kb+2, kb+3) slot0
            unsigned long long a00 = 0ull, a01 = 0ull, a10 = 0ull, a11 = 0ull;
            #pragma unroll 8
            for (int c = 0; c < C_IN; c++) {
                float2 y2 = *(const float2*)&ysm[c * YSTRIDE + yb];
                ulonglong2 kk = *(const ulonglong2*)&ksm[c * C_OUT + kb];
                unsigned long long ya = bcast2(y2.x);
                unsigned long long ybv = bcast2(y2.y);
                ffma2(a00, ya,  kk.x);
                ffma2(a01, ya,  kk.y);
                ffma2(a10, ybv, kk.x);
                ffma2(a11, ybv, kk.y);
            }

            float2 r00 = unpack2(a00), r01 = unpack2(a01);
            float2 r10 = unpack2(a10), r11 = unpack2(a11);
            float acc[2][4] = {{r00.x, r00.y, r01.x, r01.y},
                               {r10.x, r10.y, r11.x, r11.y}};

            #pragma unroll
            for (int j = 0; j < 2; j++) {
                int slot = yb + j;
                if (slot < nb) {
                    unsigned e = esm[slot];
                    float w = wsm[slot];
                    float4 o;
                    o.x = acc[j][0] + w * bsm[kb + 0];
                    o.y = acc[j][1] + w * bsm[kb + 1];
                    o.z = acc[j][2] + w * bsm[kb + 2];
                    o.w = acc[j][3] + w * bsm[kb + 3];
                    *(float4*)&g_contrib[(size_t)e * C_OUT + kb] = o;
                }
            }
        }
    }
}

// ---------------------------------------------------------------------------
// K5: deterministic reduction of the 8 corner contributions per point.
//     float4 per thread: 8 independent LDG.128 (MLP=8) + 1 STG.128.
// ---------------------------------------------------------------------------
__global__ void k_reduce(float* __restrict__ out) {
    int i = blockIdx.x * blockDim.x + threadIdx.x;   // over NPTS*16 float4s
    if (i >= NPTS * (C_OUT / 4)) return;
    int n = i >> 4, q = i & 15;

    const float4* cp = (const float4*)g_contrib;
    size_t base = (size_t)n * 8 * (C_OUT / 4) + q;

    float4 v0 = cp[base + 0 * (C_OUT / 4)];
    float4 v1 = cp[base + 1 * (C_OUT / 4)];
    float4 v2 = cp[base + 2 * (C_OUT / 4)];
    float4 v3 = cp[base + 3 * (C_OUT / 4)];
    float4 v4 = cp[base + 4 * (C_OUT / 4)];
    float4 v5 = cp[base + 5 * (C_OUT / 4)];
    float4 v6 = cp[base + 6 * (C_OUT / 4)];
    float4 v7 = cp[base + 7 * (C_OUT / 4)];

    float4 s;
    s.x = ((v0.x + v1.x) + (v2.x + v3.x)) + ((v4.x + v5.x) + (v6.x + v7.x));
    s.y = ((v0.y + v1.y) + (v2.y + v3.y)) + ((v4.y + v5.y) + (v6.y + v7.y));
    s.z = ((v0.z + v1.z) + (v2.z + v3.z)) + ((v4.z + v5.z) + (v6.z + v7.z));
    s.w = ((v0.w + v1.w) + (v2.w + v3.w)) + ((v4.w + v5.w) + (v6.w + v7.w));

    ((float4*)out)[i] = s;
}

// ---------------------------------------------------------------------------
// Launcher (graph-capturable: kernels only, default stream)
// ---------------------------------------------------------------------------
extern "C" void kernel_launch(void* const* d_in, const int* in_sizes, int n_in,
                              void* d_out, int out_size) {
    const int*   pidx    = (const int*)  d_in[0];  // (N,1) int32
    const float* pos     = (const float*)d_in[1];  // (N,3)
    const float* xs      = (const float*)d_in[2];  // (N,64)
    const float* kernels = (const float*)d_in[3];  // (4,16,16,16,64,64)
    const float* biases  = (const float*)d_in[4];  // (4,16,16,16,64)
    float* out = (float*)d_out;                    // (N,64)
    (void)in_sizes; (void)n_in; (void)out_size;

    k_zero_counts<<<(NCELLS + 255) / 256, 256>>>();
    k_prep<<<(NPTS + 255) / 256, 256>>>(pidx, pos);
    k_scan<<<1, 512>>>();
    k_scatter<<<(NENT + 255) / 256, 256>>>();
    k_cell_gemm<<<NCELLS, 128>>>(xs, kernels, biases);
    k_reduce<<<(NPTS * (C_OUT / 4) + 255) / 256, 256>>>(out);
}

// round 6
// speedup vs baseline: 1.1231x; 1.0090x over previous
#include <cuda_runtime.h>
#include <stdint.h>

// Problem constants (fixed by the dataset)
#define NPTS      32768
#define NKERN     4
#define GRID      16
#define C_IN      64
#define C_OUT     64
#define NCELLS    (NKERN * GRID * GRID * GRID)   // 16384
#define NENT      (NPTS * 8)                     // 262144

// ---------------------------------------------------------------------------
// Device scratch (static __device__ globals: allowed; no cudaMalloc anywhere)
// ---------------------------------------------------------------------------
__device__ unsigned g_counts[NCELLS];
__device__ unsigned g_offsets[NCELLS + 1];
__device__ unsigned g_cursor[NCELLS];
__device__ unsigned g_cells[NENT];     // cell id per (point,corner) entry
__device__ float    g_wts[NENT];       // trilinear weight per entry
__device__ unsigned g_sorted[NENT];    // entry ids grouped by cell
__device__ float    g_contrib[(size_t)NENT * C_OUT];  // 67MB staging (deterministic)

// packed f32x2 FMA: d = a*b + d  (SASS FFMA2 — 2 fp32 MACs per lane per issue)
__device__ __forceinline__ void ffma2(unsigned long long& d,
                                      unsigned long long a,
                                      unsigned long long b) {
    asm("fma.rn.f32x2 %0, %1, %2, %0;" : "+l"(d) : "l"(a), "l"(b));
}
__device__ __forceinline__ unsigned long long bcast2(float v) {
    unsigned long long r;
    asm("mov.b64 %0, {%1, %1};" : "=l"(r) : "f"(v));
    return r;
}
__device__ __forceinline__ float2 unpack2(unsigned long long v) {
    float2 r;
    asm("mov.b64 {%0, %1}, %2;" : "=f"(r.x), "=f"(r.y) : "l"(v));
    return r;
}

// ---------------------------------------------------------------------------
// K0: zero the histogram
// ---------------------------------------------------------------------------
__global__ void k_zero_counts() {
    int i = blockIdx.x * blockDim.x + threadIdx.x;
    if (i < NCELLS) g_counts[i] = 0u;
}

// ---------------------------------------------------------------------------
// K1: per-point corner cells + weights, histogram cells
// ---------------------------------------------------------------------------
__global__ void k_prep(const int* __restrict__ pidx,
                       const float* __restrict__ pos) {
    int n = blockIdx.x * blockDim.x + threadIdx.x;
    if (n >= NPTS) return;

    float lx = pos[n * 3 + 0] * (float)GRID - 0.5f;
    float ly = pos[n * 3 + 1] * (float)GRID - 0.5f;
    float lz = pos[n * 3 + 2] * (float)GRID - 0.5f;
    float fx = floorf(lx), fy = floorf(ly), fz = floorf(lz);
    float cwx = lx - fx, cwy = ly - fy, cwz = lz - fz;
    float fwx = 1.f - cwx, fwy = 1.f - cwy, fwz = 1.f - cwz;
    int ix = (int)fx, iy = (int)fy, iz = (int)fz;   // may be -1..15
    int pi = pidx[n];

    #pragma unroll
    for (int k = 0; k < 8; k++) {
        int bx = k & 1, by = (k >> 1) & 1, bz = (k >> 2) & 1;
        int jx = min(max(ix + bx, 0), GRID - 1);
        int jy = min(max(iy + by, 0), GRID - 1);
        int jz = min(max(iz + bz, 0), GRID - 1);
        float w = (bx ? cwx : fwx) * (by ? cwy : fwy) * (bz ? cwz : fwz);
        // reference indexes kernels[pidx, idx_z, idx_y, idx_x]
        unsigned cell = (((unsigned)pi * GRID + jz) * GRID + jy) * GRID + jx;
        g_cells[n * 8 + k] = cell;
        g_wts[n * 8 + k] = w;
        atomicAdd(&g_counts[cell], 1u);
    }
}

// ---------------------------------------------------------------------------
// K2: single-block exclusive scan of 16384 counts (512 thr x 32 elems)
// ---------------------------------------------------------------------------
__global__ void k_scan() {
    __shared__ unsigned part[512];
    int t = threadIdx.x;
    unsigned sum = 0;
    #pragma unroll 4
    for (int i = 0; i < 32; i++) sum += g_counts[t * 32 + i];
    part[t] = sum;
    __syncthreads();
    for (int off = 1; off < 512; off <<= 1) {
        unsigned v = 0;
        if (t >= off) v = part[t - off];
        __syncthreads();
        if (t >= off) part[t] += v;
        __syncthreads();
    }
    unsigned run = (t == 0) ? 0u : part[t - 1];
    #pragma unroll 4
    for (int i = 0; i < 32; i++) {
        int idx = t * 32 + i;
        g_offsets[idx] = run;
        g_cursor[idx] = run;
        run += g_counts[idx];
    }
    if (t == 511) g_offsets[NCELLS] = run;   // == NENT
}

// ---------------------------------------------------------------------------
// K3: scatter entries into cell-grouped order
// ---------------------------------------------------------------------------
__global__ void k_scatter() {
    int e = blockIdx.x * blockDim.x + threadIdx.x;
    if (e >= NENT) return;
    unsigned cell = g_cells[e];
    unsigned slot = atomicAdd(&g_cursor[cell], 1u);
    g_sorted[slot] = (unsigned)e;
}

// ---------------------------------------------------------------------------
// K4: per-cell GEMM.  One CTA of 64 threads per cell.
//     Tile: 4 slots x 4 cols per thread (16 outputs).  Per c-step a warp
//     reads only 256B of K (dedup across its 2 slot-groups, 2 wavefronts)
//     + 32B of y (1 wavefront): 6 wf/c/CTA vs 24 in the 128-thread version.
//     Inner math: 8 packed fma.rn.f32x2 per c-step (32 MACs/thread/c).
//     contrib[e][f] = w_e * (x_e @ K + b)     (written once; deterministic)
// ---------------------------------------------------------------------------
#define YSTRIDE 20   // 16 slots padded to 20 floats: keeps float4 16B-aligned

__global__ __launch_bounds__(64) void k_cell_gemm(
    const float* __restrict__ xs,
    const float* __restrict__ kernels,
    const float* __restrict__ biases) {

    int cell = blockIdx.x;
    int start = (int)g_offsets[cell];
    int nent  = (int)g_offsets[cell + 1] - start;
    if (nent == 0) return;

    __shared__ __align__(16) float ksm[C_IN * C_OUT];   // 16KB
    __shared__ __align__(16) float ysm[C_IN * YSTRIDE]; // 5KB
    __shared__ float    bsm[C_OUT];
    __shared__ float    wsm[16];
    __shared__ unsigned esm[16];

    int t = threadIdx.x;                 // 64 threads
    int fj = t & 15;                     // 16 column groups of 4 -> 64 cols
    int ei = t >> 4;                     // 4 slot groups of 4 -> 16 slots
    const int yb = ei * 4;               // first of this thread's 4 slots
    const int kb = fj * 4;               // first of this thread's 4 columns

    // stage K (coalesced float4, 16 per thread) and bias
    const float* kg = kernels + (size_t)cell * (C_IN * C_OUT);
    #pragma unroll
    for (int i = t; i < (C_IN * C_OUT) / 4; i += 64)
        ((float4*)ksm)[i] = ((const float4*)kg)[i];
    bsm[t] = biases[(size_t)cell * C_OUT + t];   // t < 64 == C_OUT

    for (int base = 0; base < nent; base += 16) {
        int nb = min(16, nent - base);

        __syncthreads();   // prior batch done reading ysm/esm; K staged (1st iter)
        if (t < 16) {
            unsigned e = 0xFFFFFFFFu;
            float w = 0.f;
            if (t < nb) { e = g_sorted[start + base + t]; w = g_wts[e]; }
            esm[t] = e;
            wsm[t] = w;
        }
        __syncthreads();

        // stage y[c][slot] = w * x[pt][c]  (thread t owns column c=t, 16 slots)
        #pragma unroll
        for (int k = 0; k < 16; k++) {
            unsigned e = esm[k];
            float v = 0.f;
            if (e != 0xFFFFFFFFu) v = wsm[k] * xs[(size_t)(e >> 3) * C_IN + t];
            ysm[t * YSTRIDE + k] = v;
        }
        __syncthreads();

        // warp0 owns slots 0-7, warp1 slots 8-15; all-padding warps skip.
        if (yb < nb) {
            // packed accumulators: a[s][p] = slot yb+s, column pair kb+2p
            unsigned long long a[4][2] = {{0,0},{0,0},{0,0},{0,0}};
            #pragma unroll 8
            for (int c = 0; c < C_IN; c++) {
                float4 y4 = *(const float4*)&ysm[c * YSTRIDE + yb];
                ulonglong2 kk = *(const ulonglong2*)&ksm[c * C_OUT + kb];
                unsigned long long y0 = bcast2(y4.x);
                unsigned long long y1 = bcast2(y4.y);
                unsigned long long y2 = bcast2(y4.z);
                unsigned long long y3 = bcast2(y4.w);
                ffma2(a[0][0], y0, kk.x); ffma2(a[0][1], y0, kk.y);
                ffma2(a[1][0], y1, kk.x); ffma2(a[1][1], y1, kk.y);
                ffma2(a[2][0], y2, kk.x); ffma2(a[2][1], y2, kk.y);
                ffma2(a[3][0], y3, kk.x); ffma2(a[3][1], y3, kk.y);
            }

            #pragma unroll
            for (int j = 0; j < 4; j++) {
                int slot = yb + j;
                if (slot < nb) {
                    unsigned e = esm[slot];
                    float w = wsm[slot];
                    float2 lo = unpack2(a[j][0]);
                    float2 hi = unpack2(a[j][1]);
                    float4 o;
                    o.x = lo.x + w * bsm[kb + 0];
                    o.y = lo.y + w * bsm[kb + 1];
                    o.z = hi.x + w * bsm[kb + 2];
                    o.w = hi.y + w * bsm[kb + 3];
                    *(float4*)&g_contrib[(size_t)e * C_OUT + kb] = o;
                }
            }
        }
    }
}

// ---------------------------------------------------------------------------
// K5: deterministic reduction of the 8 corner contributions per point.
//     float4 per thread: 8 independent LDG.128 (MLP=8) + 1 STG.128.
// ---------------------------------------------------------------------------
__global__ void k_reduce(float* __restrict__ out) {
    int i = blockIdx.x * blockDim.x + threadIdx.x;   // over NPTS*16 float4s
    if (i >= NPTS * (C_OUT / 4)) return;
    int n = i >> 4, q = i & 15;

    const float4* cp = (const float4*)g_contrib;
    size_t base = (size_t)n * 8 * (C_OUT / 4) + q;

    float4 v0 = cp[base + 0 * (C_OUT / 4)];
    float4 v1 = cp[base + 1 * (C_OUT / 4)];
    float4 v2 = cp[base + 2 * (C_OUT / 4)];
    float4 v3 = cp[base + 3 * (C_OUT / 4)];
    float4 v4 = cp[base + 4 * (C_OUT / 4)];
    float4 v5 = cp[base + 5 * (C_OUT / 4)];
    float4 v6 = cp[base + 6 * (C_OUT / 4)];
    float4 v7 = cp[base + 7 * (C_OUT / 4)];

    float4 s;
    s.x = ((v0.x + v1.x) + (v2.x + v3.x)) + ((v4.x + v5.x) + (v6.x + v7.x));
    s.y = ((v0.y + v1.y) + (v2.y + v3.y)) + ((v4.y + v5.y) + (v6.y + v7.y));
    s.z = ((v0.z + v1.z) + (v2.z + v3.z)) + ((v4.z + v5.z) + (v6.z + v7.z));
    s.w = ((v0.w + v1.w) + (v2.w + v3.w)) + ((v4.w + v5.w) + (v6.w + v7.w));

    ((float4*)out)[i] = s;
}

// ---------------------------------------------------------------------------
// Launcher (graph-capturable: kernels only, default stream)
// ---------------------------------------------------------------------------
extern "C" void kernel_launch(void* const* d_in, const int* in_sizes, int n_in,
                              void* d_out, int out_size) {
    const int*   pidx    = (const int*)  d_in[0];  // (N,1) int32
    const float* pos     = (const float*)d_in[1];  // (N,3)
    const float* xs      = (const float*)d_in[2];  // (N,64)
    const float* kernels = (const float*)d_in[3];  // (4,16,16,16,64,64)
    const float* biases  = (const float*)d_in[4];  // (4,16,16,16,64)
    float* out = (float*)d_out;                    // (N,64)
    (void)in_sizes; (void)n_in; (void)out_size;

    k_zero_counts<<<(NCELLS + 255) / 256, 256>>>();
    k_prep<<<(NPTS + 255) / 256, 256>>>(pidx, pos);
    k_scan<<<1, 512>>>();
    k_scatter<<<(NENT + 255) / 256, 256>>>();
    k_cell_gemm<<<NCELLS, 64>>>(xs, kernels, biases);
    k_reduce<<<(NPTS * (C_OUT / 4) + 255) / 256, 256>>>(out);
}